// round 14
// baseline (speedup 1.0000x reference)
#include <cuda_runtime.h>
#include <cuda_fp16.h>
#include <cuda_bf16.h>
#include <math.h>
#include <stdint.h>

// Problem dims (fixed)
#define TT 8192
#define HH 2048
#define KK 512
#define VV 512
#define OO 2048
#define CSZ 32
#define NCH (TT / CSZ)   // 256 chunks

// ===================== helpers =====================
__device__ __forceinline__ uint32_t smem_u32(const void* p) {
    uint32_t a;
    asm("{ .reg .u64 t; cvta.to.shared.u64 t, %1; cvt.u32.u64 %0, t; }"
        : "=r"(a) : "l"(p));
    return a;
}
__device__ __forceinline__ void ldm_x4(uint32_t* r, uint32_t addr) {
    asm volatile("ldmatrix.sync.aligned.m8n8.x4.shared.b16 {%0,%1,%2,%3}, [%4];"
                 : "=r"(r[0]), "=r"(r[1]), "=r"(r[2]), "=r"(r[3]) : "r"(addr));
}
__device__ __forceinline__ void mma_f16(float* d, const uint32_t* a, const uint32_t* b) {
    asm volatile(
        "mma.sync.aligned.m16n8k16.row.col.f32.f16.f16.f32 "
        "{%0,%1,%2,%3}, {%4,%5,%6,%7}, {%8,%9}, {%0,%1,%2,%3};"
        : "+f"(d[0]), "+f"(d[1]), "+f"(d[2]), "+f"(d[3])
        : "r"(a[0]), "r"(a[1]), "r"(a[2]), "r"(a[3]), "r"(b[0]), "r"(b[1]));
}
__device__ __forceinline__ void cp16(uint32_t s, const void* g) {
    asm volatile("cp.async.cg.shared.global [%0], [%1], 16;" :: "r"(s), "l"(g));
}
#define CP_COMMIT() asm volatile("cp.async.commit_group;" ::: "memory")
#define CP_WAIT0()  asm volatile("cp.async.wait_group 0;" ::: "memory")
#define CP_WAIT1()  asm volatile("cp.async.wait_group 1;" ::: "memory")

// ===================== scratch (static __device__, no allocs) =====================
static __device__ float g_Q   [TT * KK];
static __device__ float g_Ksig[TT * KK];
static __device__ float g_G   [TT * KK];
static __device__ float g_Vp  [TT * VV];
static __device__ float g_qt  [TT * KK];
static __device__ float g_kt  [TT * KK];
static __device__ float g_kh  [TT * KK];
static __device__ float g_Bend[NCH * KK];
static __device__ float g_P   [NCH * CSZ * CSZ];
static __device__ __nv_bfloat16 g_Sinb[(size_t)NCH * KK * VV];   // state entering chunk (bf16)

// fp16 split operands
static __device__ __half g_hs_hi [(size_t)TT * HH];
static __device__ __half g_hs_lo [(size_t)TT * HH];
static __device__ __half g_Wt_hi [(size_t)4 * KK * HH];   // q,k,g,v : [512,2048]
static __device__ __half g_Wt_lo [(size_t)4 * KK * HH];
static __device__ __half g_Wot_hi[(size_t)OO * VV];       // [2048,512]
static __device__ __half g_Wot_lo[(size_t)OO * VV];
static __device__ __half g_ob_hi [(size_t)TT * VV];       // outs (fp16, single plane)

// ===================== conversion kernels =====================
__global__ void cvt_split_kernel(const float* __restrict__ x,
                                 __half* __restrict__ hi,
                                 __half* __restrict__ lo, int n4)
{
    int i = blockIdx.x * 256 + threadIdx.x;
    if (i >= n4) return;
    float4 v = *((const float4*)x + i);
    __half h0 = __float2half_rn(v.x), h1 = __float2half_rn(v.y);
    __half h2 = __float2half_rn(v.z), h3 = __float2half_rn(v.w);
    __half l0 = __float2half_rn(v.x - __half2float(h0));
    __half l1 = __float2half_rn(v.y - __half2float(h1));
    __half l2 = __float2half_rn(v.z - __half2float(h2));
    __half l3 = __float2half_rn(v.w - __half2float(h3));
    ushort4 uh, ul;
    uh.x = reinterpret_cast<unsigned short&>(h0); uh.y = reinterpret_cast<unsigned short&>(h1);
    uh.z = reinterpret_cast<unsigned short&>(h2); uh.w = reinterpret_cast<unsigned short&>(h3);
    ul.x = reinterpret_cast<unsigned short&>(l0); ul.y = reinterpret_cast<unsigned short&>(l1);
    ul.z = reinterpret_cast<unsigned short&>(l2); ul.w = reinterpret_cast<unsigned short&>(l3);
    *((ushort4*)hi + i) = uh;
    *((ushort4*)lo + i) = ul;
}

// W [R, C] fp32 row-major -> out [C, R] fp16 hi/lo
__global__ void transpose_split_kernel(const float* __restrict__ W,
                                       __half* __restrict__ hi,
                                       __half* __restrict__ lo,
                                       int R, int Ccols)
{
    __shared__ float tile[32][33];
    int c0 = blockIdx.x * 32, r0 = blockIdx.y * 32;
    int tx = threadIdx.x, ty = threadIdx.y;
#pragma unroll
    for (int i = 0; i < 32; i += 8)
        tile[ty + i][tx] = W[(size_t)(r0 + ty + i) * Ccols + c0 + tx];
    __syncthreads();
#pragma unroll
    for (int i = 0; i < 32; i += 8) {
        float v = tile[tx][ty + i];
        __half h = __float2half_rn(v);
        __half l = __float2half_rn(v - __half2float(h));
        size_t o = (size_t)(c0 + ty + i) * R + r0 + tx;
        hi[o] = h; lo[o] = l;
    }
}

// ===================== tensor-core GEMM via mma.sync (fp16 split) ======
// C[M,N] = act(A @ B^T + bias); A: [M,Kd] fp16 (hi[,lo]), B: [N,Kd] fp16 (hi/lo)
// three=1: 3 passes (Ah*Bh + Ah*Bl + Al*Bh); three=0: 2 passes (Ah*Bh + Ah*Bl).
// CTA tile 128x128, BK=32, 2-stage cp.async pipeline, 2 CTAs/SM.
#define BK   32
#define BKP  40                    // padded row length (fp16 elems)
#define TILE_E (128 * BKP)         // elems per tile
#define STAGE_E (4 * TILE_E)       // Ahi,Alo,Bhi,Blo slots per stage
#define TG_SMEM_BYTES (2 * STAGE_E * 2)   // 81920

__global__ __launch_bounds__(256, 2) void tgemm_kernel(
    const __half* __restrict__ Ahi, const __half* __restrict__ Alo,
    const __half* __restrict__ Bhi, const __half* __restrict__ Blo,
    const float* __restrict__ bias, float* __restrict__ C,
    int M, int N, int Kd, int act, int three)
{
    extern __shared__ __half sm[];      // [2 stages][4 tiles][TILE_E]
    const uint32_t s0 = smem_u32(sm);

    int tid = threadIdx.x, lane = tid & 31, wid = tid >> 5;
    int bm = blockIdx.y * 128, bn = blockIdx.x * 128;
    int wm = (wid & 3) * 32, wn = (wid >> 2) * 64;

    // ldgsts slots: thread covers rows rr and rr+64, col-block qq (8 fp16 = 16B)
    int rr = tid >> 2, qq = tid & 3;
    size_t gA  = (size_t)(bm + rr) * Kd + qq * 8;
    size_t gA2 = gA + (size_t)64 * Kd;
    size_t gB  = (size_t)(bn + rr) * Kd + qq * 8;
    size_t gB2 = gB + (size_t)64 * Kd;
    uint32_t so  = (uint32_t)(rr * BKP + qq * 8) * 2;
    uint32_t so2 = so + (uint32_t)(64 * BKP) * 2;

    auto issue = [&](int ch) {
        size_t kb = (size_t)ch << 5;
        uint32_t sb = s0 + (uint32_t)(ch & 1) * (STAGE_E * 2);
        cp16(sb + 0 * (TILE_E * 2) + so,  Ahi + gA  + kb);
        cp16(sb + 0 * (TILE_E * 2) + so2, Ahi + gA2 + kb);
        if (three) {
            cp16(sb + 1 * (TILE_E * 2) + so,  Alo + gA  + kb);
            cp16(sb + 1 * (TILE_E * 2) + so2, Alo + gA2 + kb);
        }
        cp16(sb + 2 * (TILE_E * 2) + so,  Bhi + gB  + kb);
        cp16(sb + 2 * (TILE_E * 2) + so2, Bhi + gB2 + kb);
        cp16(sb + 3 * (TILE_E * 2) + so,  Blo + gB  + kb);
        cp16(sb + 3 * (TILE_E * 2) + so2, Blo + gB2 + kb);
        CP_COMMIT();
    };

    // fragment smem offsets (bytes, relative to stage base)
    uint32_t a_off = (uint32_t)((wm + (lane & 15)) * BKP + ((lane >> 4) << 3)) * 2;
    uint32_t b_off = (uint32_t)((wn + ((lane >> 4) << 3) + (lane & 7)) * BKP
                                + (((lane >> 3) & 1) << 3)) * 2;

    float acc[2][8][4];
#pragma unroll
    for (int i = 0; i < 2; i++)
#pragma unroll
        for (int j = 0; j < 8; j++)
#pragma unroll
            for (int l = 0; l < 4; l++) acc[i][j][l] = 0.f;

    const int NC = Kd >> 5;

    issue(0);
    CP_WAIT0();
    __syncthreads();

    for (int ch = 0; ch < NC; ch++) {
        if (ch + 1 < NC) issue(ch + 1);   // overlaps with compute below

        uint32_t base = s0 + (uint32_t)(ch & 1) * (STAGE_E * 2);
#pragma unroll
        for (int ks = 0; ks < 2; ks++) {
            uint32_t ksb = (uint32_t)(ks * 16) * 2;
            uint32_t ah[2][4], al[2][4];
#pragma unroll
            for (int mf = 0; mf < 2; mf++) {
                uint32_t ao = a_off + (uint32_t)(mf * 16 * BKP) * 2 + ksb;
                ldm_x4(ah[mf], base + 0 * (TILE_E * 2) + ao);
                if (three) ldm_x4(al[mf], base + 1 * (TILE_E * 2) + ao);
            }
#pragma unroll
            for (int nfp = 0; nfp < 4; nfp++) {
                uint32_t bo = b_off + (uint32_t)(nfp * 16 * BKP) * 2 + ksb;
                uint32_t bh[4], bl[4];
                ldm_x4(bh, base + 2 * (TILE_E * 2) + bo);
                ldm_x4(bl, base + 3 * (TILE_E * 2) + bo);
#pragma unroll
                for (int h = 0; h < 2; h++) {
                    int nf = nfp * 2 + h;
#pragma unroll
                    for (int mf = 0; mf < 2; mf++) {
                        mma_f16(acc[mf][nf], ah[mf], bh + 2 * h);
                        mma_f16(acc[mf][nf], ah[mf], bl + 2 * h);
                        if (three) mma_f16(acc[mf][nf], al[mf], bh + 2 * h);
                    }
                }
            }
        }

        if (ch + 1 < NC) {
            CP_WAIT0();          // next stage landed (mostly overlapped)
            __syncthreads();     // also guards buffer reuse next iteration
        }
    }

    // epilogue
    int crow = lane >> 2, ccol = (lane & 3) * 2;
#pragma unroll
    for (int mf = 0; mf < 2; mf++) {
#pragma unroll
        for (int nf = 0; nf < 8; nf++) {
            int row = bm + wm + mf * 16 + crow;
            int col = bn + wn + nf * 8 + ccol;
            float b0 = bias[col], b1 = bias[col + 1];
            float2 o0, o1;
            o0.x = acc[mf][nf][0] + b0;
            o0.y = acc[mf][nf][1] + b1;
            o1.x = acc[mf][nf][2] + b0;
            o1.y = acc[mf][nf][3] + b1;
            if (act) {
                o0.x = 1.f / (1.f + expf(-o0.x));
                o0.y = 1.f / (1.f + expf(-o0.y));
                o1.x = 1.f / (1.f + expf(-o1.x));
                o1.y = 1.f / (1.f + expf(-o1.y));
            }
            *(float2*)(C + (size_t)row * N + col)       = o0;
            *(float2*)(C + (size_t)(row + 8) * N + col) = o1;
        }
    }
}

// ===================== middle kernels =====================
__global__ void gates_kernel()
{
    int c = blockIdx.x;
    int col = threadIdx.x;
    size_t base = (size_t)c * CSZ * KK + col;
    float gs[CSZ];
    float cum = 1.f;
#pragma unroll
    for (int t = 0; t < CSZ; t++) {
        size_t idx = base + (size_t)t * KK;
        float g = g_G[idx];
        gs[t] = g;
        cum *= g;
        g_qt[idx] = g_Q[idx] * cum;
        g_kt[idx] = g_Ksig[idx] / cum;
    }
    g_Bend[c * KK + col] = cum;
    float suf = 1.f;
#pragma unroll
    for (int t = CSZ - 1; t >= 0; t--) {
        size_t idx = base + (size_t)t * KK;
        g_kh[idx] = g_Ksig[idx] * suf;
        suf *= gs[t];
    }
}

__global__ void p_kernel()
{
    int c = blockIdx.x;
    int s = threadIdx.x, t = threadIdx.y;
    int lid = t * 32 + s;
    __shared__ float Qs[CSZ][65];
    __shared__ float Ks[CSZ][65];
    float acc = 0.f;
    for (int kb = 0; kb < KK; kb += 64) {
#pragma unroll
        for (int i = 0; i < 2; i++) {
            int e = lid + i * 1024;
            int r = e >> 6, cc = e & 63;
            Qs[r][cc] = g_qt[(size_t)(c * CSZ + r) * KK + kb + cc];
            Ks[r][cc] = g_kt[(size_t)(c * CSZ + r) * KK + kb + cc];
        }
        __syncthreads();
        if (t >= s) {
#pragma unroll
            for (int kk = 0; kk < 64; kk++) acc += Qs[t][kk] * Ks[s][kk];
        }
        __syncthreads();
    }
    g_P[(c * CSZ + t) * CSZ + s] = (t >= s) ? acc : 0.f;
}

// ===================== fused U + inter-chunk scan =====================
// grid (KK/32, VV/32) = (16,16); block 128. Each block owns a 32x32 state tile
// in registers, loops over all 256 chunks: U_tile = Kh_c^T @ V_c (FFMA),
// Sin[c] = S (bf16), S = Bend[c] * S + U_tile. No U materialization.
__global__ __launch_bounds__(128) void uscan_kernel(float* __restrict__ final_state)
{
    __shared__ __align__(16) float sKh[2][CSZ][32];   // [buf][t][k]
    __shared__ __align__(16) float sV [2][CSZ][32];   // [buf][t][v]

    const int kt = blockIdx.x * 32;
    const int vt = blockIdx.y * 32;
    const int tid = threadIdx.x;
    const int k0 = (tid >> 3) * 2;   // 2 k-rows per thread
    const int v0 = (tid & 7) * 4;    // 4 v-cols per thread

    const uint32_t sKhB = smem_u32(&sKh[0][0][0]);
    const uint32_t sVB  = smem_u32(&sV[0][0][0]);
    const uint32_t BUFB = CSZ * 32 * 4;   // 4096 bytes per buffer

    float S0[4] = {0.f, 0.f, 0.f, 0.f};
    float S1[4] = {0.f, 0.f, 0.f, 0.f};

    auto issue = [&](int c, int buf) {
#pragma unroll
        for (int i = 0; i < 2; i++) {
            int e = tid + i * 128;
            int r = e >> 3, q = (e & 7) * 4;
            uint32_t off = (uint32_t)(buf) * BUFB + (uint32_t)(r * 32 + q) * 4;
            cp16(sKhB + off, g_kh + (size_t)(c * CSZ + r) * KK + kt + q);
            cp16(sVB  + off, g_Vp + (size_t)(c * CSZ + r) * VV + vt + q);
        }
        CP_COMMIT();
    };

    issue(0, 0);
    for (int c = 0; c < NCH; c++) {
        int buf = c & 1;
        if (c + 1 < NCH) { issue(c + 1, buf ^ 1); CP_WAIT1(); }
        else             { CP_WAIT0(); }
        __syncthreads();

        float b0 = g_Bend[c * KK + kt + k0];
        float b1 = g_Bend[c * KK + kt + k0 + 1];

        float U0[4] = {0.f, 0.f, 0.f, 0.f};
        float U1[4] = {0.f, 0.f, 0.f, 0.f};
#pragma unroll 8
        for (int t = 0; t < CSZ; t++) {
            float a0 = sKh[buf][t][k0];
            float a1 = sKh[buf][t][k0 + 1];
            float4 vv = *(const float4*)&sV[buf][t][v0];
            U0[0] += a0 * vv.x; U0[1] += a0 * vv.y;
            U0[2] += a0 * vv.z; U0[3] += a0 * vv.w;
            U1[0] += a1 * vv.x; U1[1] += a1 * vv.y;
            U1[2] += a1 * vv.z; U1[3] += a1 * vv.w;
        }

        // store Sin (state BEFORE this chunk) as bf16
        {
            ushort4 p0, p1;
            __nv_bfloat16 h;
            h = __float2bfloat16(S0[0]); p0.x = reinterpret_cast<unsigned short&>(h);
            h = __float2bfloat16(S0[1]); p0.y = reinterpret_cast<unsigned short&>(h);
            h = __float2bfloat16(S0[2]); p0.z = reinterpret_cast<unsigned short&>(h);
            h = __float2bfloat16(S0[3]); p0.w = reinterpret_cast<unsigned short&>(h);
            h = __float2bfloat16(S1[0]); p1.x = reinterpret_cast<unsigned short&>(h);
            h = __float2bfloat16(S1[1]); p1.y = reinterpret_cast<unsigned short&>(h);
            h = __float2bfloat16(S1[2]); p1.z = reinterpret_cast<unsigned short&>(h);
            h = __float2bfloat16(S1[3]); p1.w = reinterpret_cast<unsigned short&>(h);
            *(ushort4*)(g_Sinb + ((size_t)c * KK + kt + k0)     * VV + vt + v0) = p0;
            *(ushort4*)(g_Sinb + ((size_t)c * KK + kt + k0 + 1) * VV + vt + v0) = p1;
        }

#pragma unroll
        for (int j = 0; j < 4; j++) {
            S0[j] = b0 * S0[j] + U0[j];
            S1[j] = b1 * S1[j] + U1[j];
        }
        __syncthreads();   // compute done before next issue overwrites buf
    }

    *(float4*)(final_state + (size_t)(kt + k0)     * VV + vt + v0) = *(float4*)S0;
    *(float4*)(final_state + (size_t)(kt + k0 + 1) * VV + vt + v0) = *(float4*)S1;
}

// Out_c = Q~_c @ S_in[c] + P_c @ V_c ; emits fp16 (single plane) for final GEMM
__global__ __launch_bounds__(256) void out_kernel()
{
    int c = blockIdx.y;
    int vb = blockIdx.x * 128;
    int lid = threadIdx.x;
    int tr = lid >> 4, tc = lid & 15;
    __shared__ __align__(16) float Qs[CSZ][36];
    __shared__ __align__(16) float Ss[CSZ][132];
    __shared__ __align__(16) float Ps[CSZ][36];
    __shared__ __align__(16) float Vs[CSZ][132];
    float acc[2][8] = {};
    for (int kb = 0; kb < KK; kb += 32) {
#pragma unroll
        for (int i = 0; i < 4; i++) {
            int e = lid + i * 256;
            int r = e >> 5, cc = e & 31;
            Qs[r][cc] = g_qt[(size_t)(c * CSZ + r) * KK + kb + cc];
        }
        // Sin (bf16): 32 rows x 128 cols = 512 x (8 bf16); 2 loads/thread
#pragma unroll
        for (int i = 0; i < 2; i++) {
            int e = lid + i * 256;
            int r = e >> 4, c8 = e & 15;
            const __nv_bfloat162* p = (const __nv_bfloat162*)
                (g_Sinb + ((size_t)c * KK + kb + r) * VV + vb + c8 * 8);
            uint2 raw0 = *(const uint2*)p;
            uint2 raw1 = *((const uint2*)p + 1);
            __nv_bfloat162 b0 = *(__nv_bfloat162*)&raw0.x;
            __nv_bfloat162 b1 = *(__nv_bfloat162*)&raw0.y;
            __nv_bfloat162 b2 = *(__nv_bfloat162*)&raw1.x;
            __nv_bfloat162 b3 = *(__nv_bfloat162*)&raw1.y;
            float2 f0 = __bfloat1622float2(b0);
            float2 f1 = __bfloat1622float2(b1);
            float2 f2 = __bfloat1622float2(b2);
            float2 f3 = __bfloat1622float2(b3);
            float* d = &Ss[r][c8 * 8];
            d[0] = f0.x; d[1] = f0.y; d[2] = f1.x; d[3] = f1.y;
            d[4] = f2.x; d[5] = f2.y; d[6] = f3.x; d[7] = f3.y;
        }
        __syncthreads();
#pragma unroll
        for (int kk = 0; kk < 32; kk++) {
            float a0 = Qs[tr * 2 + 0][kk];
            float a1 = Qs[tr * 2 + 1][kk];
            float4 w0 = *(const float4*)&Ss[kk][tc * 8];
            float4 w1 = *(const float4*)&Ss[kk][tc * 8 + 4];
            acc[0][0] += a0 * w0.x; acc[0][1] += a0 * w0.y;
            acc[0][2] += a0 * w0.z; acc[0][3] += a0 * w0.w;
            acc[0][4] += a0 * w1.x; acc[0][5] += a0 * w1.y;
            acc[0][6] += a0 * w1.z; acc[0][7] += a0 * w1.w;
            acc[1][0] += a1 * w0.x; acc[1][1] += a1 * w0.y;
            acc[1][2] += a1 * w0.z; acc[1][3] += a1 * w0.w;
            acc[1][4] += a1 * w1.x; acc[1][5] += a1 * w1.y;
            acc[1][6] += a1 * w1.z; acc[1][7] += a1 * w1.w;
        }
        __syncthreads();
    }
#pragma unroll
    for (int i = 0; i < 4; i++) {
        int e = lid + i * 256;
        int r = e >> 5, cc = e & 31;
        Ps[r][cc] = g_P[(c * CSZ + r) * CSZ + cc];
    }
#pragma unroll
    for (int i = 0; i < 4; i++) {
        int e = lid + i * 256;
        int r = e >> 5, c4 = e & 31;
        float4 v = *(const float4*)(g_Vp + (size_t)(c * CSZ + r) * VV + vb + c4 * 4);
        *(float4*)(&Vs[r][c4 * 4]) = v;
    }
    __syncthreads();
#pragma unroll
    for (int ss = 0; ss < CSZ; ss++) {
        float a0 = Ps[tr * 2 + 0][ss];
        float a1 = Ps[tr * 2 + 1][ss];
        float4 w0 = *(const float4*)&Vs[ss][tc * 8];
        float4 w1 = *(const float4*)&Vs[ss][tc * 8 + 4];
        acc[0][0] += a0 * w0.x; acc[0][1] += a0 * w0.y;
        acc[0][2] += a0 * w0.z; acc[0][3] += a0 * w0.w;
        acc[0][4] += a0 * w1.x; acc[0][5] += a0 * w1.y;
        acc[0][6] += a0 * w1.z; acc[0][7] += a0 * w1.w;
        acc[1][0] += a1 * w0.x; acc[1][1] += a1 * w0.y;
        acc[1][2] += a1 * w0.z; acc[1][3] += a1 * w0.w;
        acc[1][4] += a1 * w1.x; acc[1][5] += a1 * w1.y;
        acc[1][6] += a1 * w1.z; acc[1][7] += a1 * w1.w;
    }
    // write fp16 (single plane — final GEMM runs 2-pass, A needs hi only)
#pragma unroll
    for (int i = 0; i < 2; i++) {
        int t = tr * 2 + i;
        size_t o = (size_t)(c * CSZ + t) * VV + vb + tc * 8;
        unsigned short ph[8];
#pragma unroll
        for (int j = 0; j < 8; j++) {
            __half h = __float2half_rn(acc[i][j]);
            ph[j] = reinterpret_cast<unsigned short&>(h);
        }
        *(uint4*)(g_ob_hi + o) = *(uint4*)ph;
    }
}

// ===================== launch =====================
extern "C" void kernel_launch(void* const* d_in, const int* in_sizes, int n_in,
                              void* d_out, int out_size)
{
    const float* hs = (const float*)d_in[0];
    const float* Wq = (const float*)d_in[1];
    const float* bq = (const float*)d_in[2];
    const float* Wk = (const float*)d_in[3];
    const float* bk = (const float*)d_in[4];
    const float* Wv = (const float*)d_in[5];
    const float* bv = (const float*)d_in[6];
    const float* Wg = (const float*)d_in[7];
    const float* bg = (const float*)d_in[8];
    const float* Wo = (const float*)d_in[9];
    const float* bo = (const float*)d_in[10];
    float* out = (float*)d_out;

    float *pQ, *pK, *pG, *pV;
    cudaGetSymbolAddress((void**)&pQ, g_Q);
    cudaGetSymbolAddress((void**)&pK, g_Ksig);
    cudaGetSymbolAddress((void**)&pG, g_G);
    cudaGetSymbolAddress((void**)&pV, g_Vp);

    __half *hsh, *hsl, *wth, *wtl, *woh, *wol, *obh;
    cudaGetSymbolAddress((void**)&hsh, g_hs_hi);
    cudaGetSymbolAddress((void**)&hsl, g_hs_lo);
    cudaGetSymbolAddress((void**)&wth, g_Wt_hi);
    cudaGetSymbolAddress((void**)&wtl, g_Wt_lo);
    cudaGetSymbolAddress((void**)&woh, g_Wot_hi);
    cudaGetSymbolAddress((void**)&wol, g_Wot_lo);
    cudaGetSymbolAddress((void**)&obh, g_ob_hi);

    cudaFuncSetAttribute(tgemm_kernel,
                         cudaFuncAttributeMaxDynamicSharedMemorySize, TG_SMEM_BYTES);

    // convert hidden_state + transpose/convert weights (fp16 hi/lo)
    {
        int n4 = (TT * HH) / 4;
        cvt_split_kernel<<<(n4 + 255) / 256, 256>>>(hs, hsh, hsl, n4);
    }
    const size_t WSTRIDE = (size_t)KK * HH;
    transpose_split_kernel<<<dim3(KK / 32, HH / 32), dim3(32, 8)>>>(Wq, wth + 0 * WSTRIDE, wtl + 0 * WSTRIDE, HH, KK);
    transpose_split_kernel<<<dim3(KK / 32, HH / 32), dim3(32, 8)>>>(Wk, wth + 1 * WSTRIDE, wtl + 1 * WSTRIDE, HH, KK);
    transpose_split_kernel<<<dim3(KK / 32, HH / 32), dim3(32, 8)>>>(Wg, wth + 2 * WSTRIDE, wtl + 2 * WSTRIDE, HH, KK);
    transpose_split_kernel<<<dim3(KK / 32, HH / 32), dim3(32, 8)>>>(Wv, wth + 3 * WSTRIDE, wtl + 3 * WSTRIDE, HH, KK);
    transpose_split_kernel<<<dim3(OO / 32, VV / 32), dim3(32, 8)>>>(Wo, woh, wol, VV, OO);

    // projections: q,v 2-pass (no gate compounding); k,g 3-pass (sigmoid/gates)
    dim3 gproj(KK / 128, TT / 128);   // (4, 64)
    tgemm_kernel<<<gproj, 256, TG_SMEM_BYTES>>>(hsh, hsl, wth + 0 * WSTRIDE, wtl + 0 * WSTRIDE, bq, pQ, TT, KK, HH, 0, 0);
    tgemm_kernel<<<gproj, 256, TG_SMEM_BYTES>>>(hsh, hsl, wth + 1 * WSTRIDE, wtl + 1 * WSTRIDE, bk, pK, TT, KK, HH, 1, 1);
    tgemm_kernel<<<gproj, 256, TG_SMEM_BYTES>>>(hsh, hsl, wth + 2 * WSTRIDE, wtl + 2 * WSTRIDE, bg, pG, TT, KK, HH, 1, 1);
    tgemm_kernel<<<gproj, 256, TG_SMEM_BYTES>>>(hsh, hsl, wth + 3 * WSTRIDE, wtl + 3 * WSTRIDE, bv, pV, TT, VV, HH, 0, 0);

    gates_kernel<<<NCH, KK>>>();
    p_kernel<<<NCH, dim3(32, 32)>>>();
    uscan_kernel<<<dim3(KK / 32, VV / 32), 128>>>(out + (size_t)TT * OO);
    out_kernel<<<dim3(VV / 128, NCH), 256>>>();

    // output GEMM: 2-pass (outs hi-only; Alo arg unused)
    tgemm_kernel<<<dim3(OO / 128, TT / 128), 256, TG_SMEM_BYTES>>>(
        obh, obh, woh, wol, bo, out, TT, OO, VV, 0, 0);
}

// round 15
// speedup vs baseline: 1.0972x; 1.0972x over previous
#include <cuda_runtime.h>
#include <cuda_fp16.h>
#include <cuda_bf16.h>
#include <math.h>
#include <stdint.h>

// Problem dims (fixed)
#define TT 8192
#define HH 2048
#define KK 512
#define VV 512
#define OO 2048
#define CSZ 32
#define NCH (TT / CSZ)   // 256 chunks
#define NPROJ 2048       // q|k|g|v concatenated

// ===================== helpers =====================
__device__ __forceinline__ uint32_t smem_u32(const void* p) {
    uint32_t a;
    asm("{ .reg .u64 t; cvta.to.shared.u64 t, %1; cvt.u32.u64 %0, t; }"
        : "=r"(a) : "l"(p));
    return a;
}
__device__ __forceinline__ void ldm_x4(uint32_t* r, uint32_t addr) {
    asm volatile("ldmatrix.sync.aligned.m8n8.x4.shared.b16 {%0,%1,%2,%3}, [%4];"
                 : "=r"(r[0]), "=r"(r[1]), "=r"(r[2]), "=r"(r[3]) : "r"(addr));
}
__device__ __forceinline__ void mma_f16(float* d, const uint32_t* a, const uint32_t* b) {
    asm volatile(
        "mma.sync.aligned.m16n8k16.row.col.f32.f16.f16.f32 "
        "{%0,%1,%2,%3}, {%4,%5,%6,%7}, {%8,%9}, {%0,%1,%2,%3};"
        : "+f"(d[0]), "+f"(d[1]), "+f"(d[2]), "+f"(d[3])
        : "r"(a[0]), "r"(a[1]), "r"(a[2]), "r"(a[3]), "r"(b[0]), "r"(b[1]));
}
__device__ __forceinline__ void cp16(uint32_t s, const void* g) {
    asm volatile("cp.async.cg.shared.global [%0], [%1], 16;" :: "r"(s), "l"(g));
}
#define CP_COMMIT() asm volatile("cp.async.commit_group;" ::: "memory")
#define CP_WAIT0()  asm volatile("cp.async.wait_group 0;" ::: "memory")
#define CP_WAIT1()  asm volatile("cp.async.wait_group 1;" ::: "memory")

// ===================== scratch (static __device__, no allocs) =====================
static __device__ float g_QKGV[(size_t)TT * NPROJ];   // q|k|g|v concat, row stride 2048
static __device__ float g_qt  [TT * KK];
static __device__ float g_kt  [TT * KK];
static __device__ float g_kh  [TT * KK];
static __device__ float g_Bend[NCH * KK];
static __device__ float g_P   [NCH * CSZ * CSZ];
static __device__ float g_bcat[NPROJ];
static __device__ __nv_bfloat16 g_Sinb[(size_t)NCH * KK * VV];   // state entering chunk (bf16)

// fp16 split operands
static __device__ __half g_hs_hi [(size_t)TT * HH];
static __device__ __half g_hs_lo [(size_t)TT * HH];
static __device__ __half g_Wt_hi [(size_t)4 * KK * HH];   // stacked Wq,Wk,Wg,Wv^T : [2048,2048]
static __device__ __half g_Wt_lo [(size_t)4 * KK * HH];
static __device__ __half g_Wot_hi[(size_t)OO * VV];       // [2048,512]
static __device__ __half g_Wot_lo[(size_t)OO * VV];
static __device__ __half g_ob_hi [(size_t)TT * VV];
static __device__ __half g_ob_lo [(size_t)TT * VV];

// ===================== small prep kernels =====================
__global__ void biascat_kernel(const float* __restrict__ bq, const float* __restrict__ bk,
                               const float* __restrict__ bg, const float* __restrict__ bv)
{
    int i = blockIdx.x * 256 + threadIdx.x;   // 0..2047
    float v;
    int p = i >> 9, c = i & 511;
    if (p == 0) v = bq[c]; else if (p == 1) v = bk[c];
    else if (p == 2) v = bg[c]; else v = bv[c];
    g_bcat[i] = v;
}

__global__ void cvt_split_kernel(const float* __restrict__ x,
                                 __half* __restrict__ hi,
                                 __half* __restrict__ lo, int n4)
{
    int i = blockIdx.x * 256 + threadIdx.x;
    if (i >= n4) return;
    float4 v = *((const float4*)x + i);
    __half h0 = __float2half_rn(v.x), h1 = __float2half_rn(v.y);
    __half h2 = __float2half_rn(v.z), h3 = __float2half_rn(v.w);
    __half l0 = __float2half_rn(v.x - __half2float(h0));
    __half l1 = __float2half_rn(v.y - __half2float(h1));
    __half l2 = __float2half_rn(v.z - __half2float(h2));
    __half l3 = __float2half_rn(v.w - __half2float(h3));
    ushort4 uh, ul;
    uh.x = reinterpret_cast<unsigned short&>(h0); uh.y = reinterpret_cast<unsigned short&>(h1);
    uh.z = reinterpret_cast<unsigned short&>(h2); uh.w = reinterpret_cast<unsigned short&>(h3);
    ul.x = reinterpret_cast<unsigned short&>(l0); ul.y = reinterpret_cast<unsigned short&>(l1);
    ul.z = reinterpret_cast<unsigned short&>(l2); ul.w = reinterpret_cast<unsigned short&>(l3);
    *((ushort4*)hi + i) = uh;
    *((ushort4*)lo + i) = ul;
}

// W [R, C] fp32 row-major -> out [C, R] fp16 hi/lo (single weight)
__global__ void transpose_split_kernel(const float* __restrict__ W,
                                       __half* __restrict__ hi,
                                       __half* __restrict__ lo,
                                       int R, int Ccols)
{
    __shared__ float tile[32][33];
    int c0 = blockIdx.x * 32, r0 = blockIdx.y * 32;
    int tx = threadIdx.x, ty = threadIdx.y;
#pragma unroll
    for (int i = 0; i < 32; i += 8)
        tile[ty + i][tx] = W[(size_t)(r0 + ty + i) * Ccols + c0 + tx];
    __syncthreads();
#pragma unroll
    for (int i = 0; i < 32; i += 8) {
        float v = tile[tx][ty + i];
        __half h = __float2half_rn(v);
        __half l = __float2half_rn(v - __half2float(h));
        size_t o = (size_t)(c0 + ty + i) * R + r0 + tx;
        hi[o] = h; lo[o] = l;
    }
}

// batched: transpose/split Wq,Wk,Wg,Wv [2048,512] -> stacked [4*512, 2048]
__global__ void transpose_split4_kernel(const float* __restrict__ W0, const float* __restrict__ W1,
                                        const float* __restrict__ W2, const float* __restrict__ W3)
{
    __shared__ float tile[32][33];
    const float* W = (blockIdx.z == 0) ? W0 : (blockIdx.z == 1) ? W1
                   : (blockIdx.z == 2) ? W2 : W3;
    __half* hi = g_Wt_hi + (size_t)blockIdx.z * KK * HH;
    __half* lo = g_Wt_lo + (size_t)blockIdx.z * KK * HH;
    int c0 = blockIdx.x * 32, r0 = blockIdx.y * 32;   // c: out-col (K dim), r: H dim
    int tx = threadIdx.x, ty = threadIdx.y;
#pragma unroll
    for (int i = 0; i < 32; i += 8)
        tile[ty + i][tx] = W[(size_t)(r0 + ty + i) * KK + c0 + tx];
    __syncthreads();
#pragma unroll
    for (int i = 0; i < 32; i += 8) {
        float v = tile[tx][ty + i];
        __half h = __float2half_rn(v);
        __half l = __float2half_rn(v - __half2float(h));
        size_t o = (size_t)(c0 + ty + i) * HH + r0 + tx;
        hi[o] = h; lo[o] = l;
    }
}

// ===================== tensor-core GEMM via mma.sync (fp16 hi/lo, 3 passes) ======
// C[M,N] = act(A @ B^T + bias); A: [M,Kd] fp16 hi/lo, B: [N,Kd] fp16 hi/lo
// actmode: 0 none; 1 sigmoid all; 2 sigmoid iff (blockIdx.x>>2) in {1,2} (k,g ranges)
// CTA tile 128x128, BK=32, 2-stage cp.async pipeline, 2 CTAs/SM.
#define BK   32
#define BKP  40                    // padded row length (fp16 elems)
#define TILE_E (128 * BKP)         // elems per tile
#define STAGE_E (4 * TILE_E)       // Ahi,Alo,Bhi,Blo per stage
#define TG_SMEM_BYTES (2 * STAGE_E * 2)   // 81920

__global__ __launch_bounds__(256, 2) void tgemm_kernel(
    const __half* __restrict__ Ahi, const __half* __restrict__ Alo,
    const __half* __restrict__ Bhi, const __half* __restrict__ Blo,
    const float* __restrict__ bias, float* __restrict__ C,
    int M, int N, int Kd, int actmode)
{
    extern __shared__ __half sm[];      // [2 stages][4 tiles][TILE_E]
    const uint32_t s0 = smem_u32(sm);

    int tid = threadIdx.x, lane = tid & 31, wid = tid >> 5;
    int bm = blockIdx.y * 128, bn = blockIdx.x * 128;
    int wm = (wid & 3) * 32, wn = (wid >> 2) * 64;
    int act = (actmode == 1) || (actmode == 2 && ((blockIdx.x >> 2) == 1 || (blockIdx.x >> 2) == 2));

    // ldgsts slots: thread covers rows rr and rr+64, col-block qq (8 fp16 = 16B)
    int rr = tid >> 2, qq = tid & 3;
    size_t gA  = (size_t)(bm + rr) * Kd + qq * 8;
    size_t gA2 = gA + (size_t)64 * Kd;
    size_t gB  = (size_t)(bn + rr) * Kd + qq * 8;
    size_t gB2 = gB + (size_t)64 * Kd;
    uint32_t so  = (uint32_t)(rr * BKP + qq * 8) * 2;
    uint32_t so2 = so + (uint32_t)(64 * BKP) * 2;

    auto issue = [&](int ch) {
        size_t kb = (size_t)ch << 5;
        uint32_t sb = s0 + (uint32_t)(ch & 1) * (STAGE_E * 2);
        cp16(sb + 0 * (TILE_E * 2) + so,  Ahi + gA  + kb);
        cp16(sb + 0 * (TILE_E * 2) + so2, Ahi + gA2 + kb);
        cp16(sb + 1 * (TILE_E * 2) + so,  Alo + gA  + kb);
        cp16(sb + 1 * (TILE_E * 2) + so2, Alo + gA2 + kb);
        cp16(sb + 2 * (TILE_E * 2) + so,  Bhi + gB  + kb);
        cp16(sb + 2 * (TILE_E * 2) + so2, Bhi + gB2 + kb);
        cp16(sb + 3 * (TILE_E * 2) + so,  Blo + gB  + kb);
        cp16(sb + 3 * (TILE_E * 2) + so2, Blo + gB2 + kb);
        CP_COMMIT();
    };

    // fragment smem offsets (bytes, relative to stage base)
    uint32_t a_off = (uint32_t)((wm + (lane & 15)) * BKP + ((lane >> 4) << 3)) * 2;
    uint32_t b_off = (uint32_t)((wn + ((lane >> 4) << 3) + (lane & 7)) * BKP
                                + (((lane >> 3) & 1) << 3)) * 2;

    float acc[2][8][4];
#pragma unroll
    for (int i = 0; i < 2; i++)
#pragma unroll
        for (int j = 0; j < 8; j++)
#pragma unroll
            for (int l = 0; l < 4; l++) acc[i][j][l] = 0.f;

    const int NC = Kd >> 5;

    issue(0);
    CP_WAIT0();
    __syncthreads();

    for (int ch = 0; ch < NC; ch++) {
        if (ch + 1 < NC) issue(ch + 1);   // overlaps with compute below

        uint32_t base = s0 + (uint32_t)(ch & 1) * (STAGE_E * 2);
#pragma unroll
        for (int ks = 0; ks < 2; ks++) {
            uint32_t ksb = (uint32_t)(ks * 16) * 2;
            uint32_t ah[2][4], al[2][4];
#pragma unroll
            for (int mf = 0; mf < 2; mf++) {
                uint32_t ao = a_off + (uint32_t)(mf * 16 * BKP) * 2 + ksb;
                ldm_x4(ah[mf], base + 0 * (TILE_E * 2) + ao);
                ldm_x4(al[mf], base + 1 * (TILE_E * 2) + ao);
            }
#pragma unroll
            for (int nfp = 0; nfp < 4; nfp++) {
                uint32_t bo = b_off + (uint32_t)(nfp * 16 * BKP) * 2 + ksb;
                uint32_t bh[4], bl[4];
                ldm_x4(bh, base + 2 * (TILE_E * 2) + bo);
                ldm_x4(bl, base + 3 * (TILE_E * 2) + bo);
#pragma unroll
                for (int h = 0; h < 2; h++) {
                    int nf = nfp * 2 + h;
#pragma unroll
                    for (int mf = 0; mf < 2; mf++) {
                        mma_f16(acc[mf][nf], ah[mf], bh + 2 * h);
                        mma_f16(acc[mf][nf], ah[mf], bl + 2 * h);
                        mma_f16(acc[mf][nf], al[mf], bh + 2 * h);
                    }
                }
            }
        }

        if (ch + 1 < NC) {
            CP_WAIT0();          // next stage landed (mostly overlapped)
            __syncthreads();     // also guards buffer reuse next iteration
        }
    }

    // epilogue
    int crow = lane >> 2, ccol = (lane & 3) * 2;
#pragma unroll
    for (int mf = 0; mf < 2; mf++) {
#pragma unroll
        for (int nf = 0; nf < 8; nf++) {
            int row = bm + wm + mf * 16 + crow;
            int col = bn + wn + nf * 8 + ccol;
            float b0 = bias[col], b1 = bias[col + 1];
            float2 o0, o1;
            o0.x = acc[mf][nf][0] + b0;
            o0.y = acc[mf][nf][1] + b1;
            o1.x = acc[mf][nf][2] + b0;
            o1.y = acc[mf][nf][3] + b1;
            if (act) {
                o0.x = 1.f / (1.f + expf(-o0.x));
                o0.y = 1.f / (1.f + expf(-o0.y));
                o1.x = 1.f / (1.f + expf(-o1.x));
                o1.y = 1.f / (1.f + expf(-o1.y));
            }
            *(float2*)(C + (size_t)row * N + col)       = o0;
            *(float2*)(C + (size_t)(row + 8) * N + col) = o1;
        }
    }
}

// ===================== middle kernels =====================
// reads q,k,g from concat buffer (stride NPROJ)
__global__ void gates_kernel()
{
    int c = blockIdx.x;
    int col = threadIdx.x;
    size_t base  = (size_t)c * CSZ * NPROJ + col;   // q plane
    size_t baseo = (size_t)c * CSZ * KK + col;      // outputs
    float gs[CSZ];
    float cum = 1.f;
#pragma unroll
    for (int t = 0; t < CSZ; t++) {
        size_t idx = base + (size_t)t * NPROJ;
        size_t odx = baseo + (size_t)t * KK;
        float g = g_QKGV[idx + 1024];
        float k = g_QKGV[idx + 512];
        gs[t] = g;
        cum *= g;
        g_qt[odx] = g_QKGV[idx] * cum;
        g_kt[odx] = k / cum;
    }
    g_Bend[c * KK + col] = cum;
    float suf = 1.f;
#pragma unroll
    for (int t = CSZ - 1; t >= 0; t--) {
        size_t idx = base + (size_t)t * NPROJ;
        size_t odx = baseo + (size_t)t * KK;
        g_kh[odx] = g_QKGV[idx + 512] * suf;
        suf *= gs[t];
    }
}

__global__ void p_kernel()
{
    int c = blockIdx.x;
    int s = threadIdx.x, t = threadIdx.y;
    int lid = t * 32 + s;
    __shared__ float Qs[CSZ][65];
    __shared__ float Ks[CSZ][65];
    float acc = 0.f;
    for (int kb = 0; kb < KK; kb += 64) {
#pragma unroll
        for (int i = 0; i < 2; i++) {
            int e = lid + i * 1024;
            int r = e >> 6, cc = e & 63;
            Qs[r][cc] = g_qt[(size_t)(c * CSZ + r) * KK + kb + cc];
            Ks[r][cc] = g_kt[(size_t)(c * CSZ + r) * KK + kb + cc];
        }
        __syncthreads();
        if (t >= s) {
#pragma unroll
            for (int kk = 0; kk < 64; kk++) acc += Qs[t][kk] * Ks[s][kk];
        }
        __syncthreads();
    }
    g_P[(c * CSZ + t) * CSZ + s] = (t >= s) ? acc : 0.f;
}

// ===================== fused U + inter-chunk scan =====================
__global__ __launch_bounds__(128) void uscan_kernel(float* __restrict__ final_state)
{
    __shared__ __align__(16) float sKh[2][CSZ][32];   // [buf][t][k]
    __shared__ __align__(16) float sV [2][CSZ][32];   // [buf][t][v]

    const int kt = blockIdx.x * 32;
    const int vt = blockIdx.y * 32;
    const int tid = threadIdx.x;
    const int k0 = (tid >> 3) * 2;   // 2 k-rows per thread
    const int v0 = (tid & 7) * 4;    // 4 v-cols per thread

    const uint32_t sKhB = smem_u32(&sKh[0][0][0]);
    const uint32_t sVB  = smem_u32(&sV[0][0][0]);
    const uint32_t BUFB = CSZ * 32 * 4;   // 4096 bytes per buffer

    float S0[4] = {0.f, 0.f, 0.f, 0.f};
    float S1[4] = {0.f, 0.f, 0.f, 0.f};

    auto issue = [&](int c, int buf) {
#pragma unroll
        for (int i = 0; i < 2; i++) {
            int e = tid + i * 128;
            int r = e >> 3, q = (e & 7) * 4;
            uint32_t off = (uint32_t)(buf) * BUFB + (uint32_t)(r * 32 + q) * 4;
            cp16(sKhB + off, g_kh + (size_t)(c * CSZ + r) * KK + kt + q);
            cp16(sVB  + off, g_QKGV + (size_t)(c * CSZ + r) * NPROJ + 1536 + vt + q);
        }
        CP_COMMIT();
    };

    issue(0, 0);
    for (int c = 0; c < NCH; c++) {
        int buf = c & 1;
        if (c + 1 < NCH) { issue(c + 1, buf ^ 1); CP_WAIT1(); }
        else             { CP_WAIT0(); }
        __syncthreads();

        float b0 = g_Bend[c * KK + kt + k0];
        float b1 = g_Bend[c * KK + kt + k0 + 1];

        float U0[4] = {0.f, 0.f, 0.f, 0.f};
        float U1[4] = {0.f, 0.f, 0.f, 0.f};
#pragma unroll 8
        for (int t = 0; t < CSZ; t++) {
            float a0 = sKh[buf][t][k0];
            float a1 = sKh[buf][t][k0 + 1];
            float4 vv = *(const float4*)&sV[buf][t][v0];
            U0[0] += a0 * vv.x; U0[1] += a0 * vv.y;
            U0[2] += a0 * vv.z; U0[3] += a0 * vv.w;
            U1[0] += a1 * vv.x; U1[1] += a1 * vv.y;
            U1[2] += a1 * vv.z; U1[3] += a1 * vv.w;
        }

        // store Sin (state BEFORE this chunk) as bf16
        {
            ushort4 p0, p1;
            __nv_bfloat16 h;
            h = __float2bfloat16(S0[0]); p0.x = reinterpret_cast<unsigned short&>(h);
            h = __float2bfloat16(S0[1]); p0.y = reinterpret_cast<unsigned short&>(h);
            h = __float2bfloat16(S0[2]); p0.z = reinterpret_cast<unsigned short&>(h);
            h = __float2bfloat16(S0[3]); p0.w = reinterpret_cast<unsigned short&>(h);
            h = __float2bfloat16(S1[0]); p1.x = reinterpret_cast<unsigned short&>(h);
            h = __float2bfloat16(S1[1]); p1.y = reinterpret_cast<unsigned short&>(h);
            h = __float2bfloat16(S1[2]); p1.z = reinterpret_cast<unsigned short&>(h);
            h = __float2bfloat16(S1[3]); p1.w = reinterpret_cast<unsigned short&>(h);
            *(ushort4*)(g_Sinb + ((size_t)c * KK + kt + k0)     * VV + vt + v0) = p0;
            *(ushort4*)(g_Sinb + ((size_t)c * KK + kt + k0 + 1) * VV + vt + v0) = p1;
        }

#pragma unroll
        for (int j = 0; j < 4; j++) {
            S0[j] = b0 * S0[j] + U0[j];
            S1[j] = b1 * S1[j] + U1[j];
        }
        __syncthreads();   // compute done before next issue overwrites buf
    }

    *(float4*)(final_state + (size_t)(kt + k0)     * VV + vt + v0) = *(float4*)S0;
    *(float4*)(final_state + (size_t)(kt + k0 + 1) * VV + vt + v0) = *(float4*)S1;
}

// Out_c = Q~_c @ S_in[c] + P_c @ V_c ; emits fp16 hi/lo for final GEMM (3-pass)
__global__ __launch_bounds__(256) void out_kernel()
{
    int c = blockIdx.y;
    int vb = blockIdx.x * 128;
    int lid = threadIdx.x;
    int tr = lid >> 4, tc = lid & 15;
    __shared__ __align__(16) float Qs[CSZ][36];
    __shared__ __align__(16) float Ss[CSZ][132];
    __shared__ __align__(16) float Ps[CSZ][36];
    __shared__ __align__(16) float Vs[CSZ][132];
    float acc[2][8] = {};
    for (int kb = 0; kb < KK; kb += 32) {
#pragma unroll
        for (int i = 0; i < 4; i++) {
            int e = lid + i * 256;
            int r = e >> 5, cc = e & 31;
            Qs[r][cc] = g_qt[(size_t)(c * CSZ + r) * KK + kb + cc];
        }
#pragma unroll
        for (int i = 0; i < 2; i++) {
            int e = lid + i * 256;
            int r = e >> 4, c8 = e & 15;
            const __nv_bfloat162* p = (const __nv_bfloat162*)
                (g_Sinb + ((size_t)c * KK + kb + r) * VV + vb + c8 * 8);
            uint2 raw0 = *(const uint2*)p;
            uint2 raw1 = *((const uint2*)p + 1);
            __nv_bfloat162 b0 = *(__nv_bfloat162*)&raw0.x;
            __nv_bfloat162 b1 = *(__nv_bfloat162*)&raw0.y;
            __nv_bfloat162 b2 = *(__nv_bfloat162*)&raw1.x;
            __nv_bfloat162 b3 = *(__nv_bfloat162*)&raw1.y;
            float2 f0 = __bfloat1622float2(b0);
            float2 f1 = __bfloat1622float2(b1);
            float2 f2 = __bfloat1622float2(b2);
            float2 f3 = __bfloat1622float2(b3);
            float* d = &Ss[r][c8 * 8];
            d[0] = f0.x; d[1] = f0.y; d[2] = f1.x; d[3] = f1.y;
            d[4] = f2.x; d[5] = f2.y; d[6] = f3.x; d[7] = f3.y;
        }
        __syncthreads();
#pragma unroll
        for (int kk = 0; kk < 32; kk++) {
            float a0 = Qs[tr * 2 + 0][kk];
            float a1 = Qs[tr * 2 + 1][kk];
            float4 w0 = *(const float4*)&Ss[kk][tc * 8];
            float4 w1 = *(const float4*)&Ss[kk][tc * 8 + 4];
            acc[0][0] += a0 * w0.x; acc[0][1] += a0 * w0.y;
            acc[0][2] += a0 * w0.z; acc[0][3] += a0 * w0.w;
            acc[0][4] += a0 * w1.x; acc[0][5] += a0 * w1.y;
            acc[0][6] += a0 * w1.z; acc[0][7] += a0 * w1.w;
            acc[1][0] += a1 * w0.x; acc[1][1] += a1 * w0.y;
            acc[1][2] += a1 * w0.z; acc[1][3] += a1 * w0.w;
            acc[1][4] += a1 * w1.x; acc[1][5] += a1 * w1.y;
            acc[1][6] += a1 * w1.z; acc[1][7] += a1 * w1.w;
        }
        __syncthreads();
    }
#pragma unroll
    for (int i = 0; i < 4; i++) {
        int e = lid + i * 256;
        int r = e >> 5, cc = e & 31;
        Ps[r][cc] = g_P[(c * CSZ + r) * CSZ + cc];
    }
#pragma unroll
    for (int i = 0; i < 4; i++) {
        int e = lid + i * 256;
        int r = e >> 5, c4 = e & 31;
        float4 v = *(const float4*)(g_QKGV + (size_t)(c * CSZ + r) * NPROJ + 1536 + vb + c4 * 4);
        *(float4*)(&Vs[r][c4 * 4]) = v;
    }
    __syncthreads();
#pragma unroll
    for (int ss = 0; ss < CSZ; ss++) {
        float a0 = Ps[tr * 2 + 0][ss];
        float a1 = Ps[tr * 2 + 1][ss];
        float4 w0 = *(const float4*)&Vs[ss][tc * 8];
        float4 w1 = *(const float4*)&Vs[ss][tc * 8 + 4];
        acc[0][0] += a0 * w0.x; acc[0][1] += a0 * w0.y;
        acc[0][2] += a0 * w0.z; acc[0][3] += a0 * w0.w;
        acc[0][4] += a0 * w1.x; acc[0][5] += a0 * w1.y;
        acc[0][6] += a0 * w1.z; acc[0][7] += a0 * w1.w;
        acc[1][0] += a1 * w0.x; acc[1][1] += a1 * w0.y;
        acc[1][2] += a1 * w0.z; acc[1][3] += a1 * w0.w;
        acc[1][4] += a1 * w1.x; acc[1][5] += a1 * w1.y;
        acc[1][6] += a1 * w1.z; acc[1][7] += a1 * w1.w;
    }
    // write fp16 hi/lo (final GEMM runs 3-pass)
#pragma unroll
    for (int i = 0; i < 2; i++) {
        int t = tr * 2 + i;
        size_t o = (size_t)(c * CSZ + t) * VV + vb + tc * 8;
        unsigned short ph[8], pl[8];
#pragma unroll
        for (int j = 0; j < 8; j++) {
            float v = acc[i][j];
            __half h = __float2half_rn(v);
            __half l = __float2half_rn(v - __half2float(h));
            ph[j] = reinterpret_cast<unsigned short&>(h);
            pl[j] = reinterpret_cast<unsigned short&>(l);
        }
        *(uint4*)(g_ob_hi + o) = *(uint4*)ph;
        *(uint4*)(g_ob_lo + o) = *(uint4*)pl;
    }
}

// ===================== launch =====================
extern "C" void kernel_launch(void* const* d_in, const int* in_sizes, int n_in,
                              void* d_out, int out_size)
{
    const float* hs = (const float*)d_in[0];
    const float* Wq = (const float*)d_in[1];
    const float* bq = (const float*)d_in[2];
    const float* Wk = (const float*)d_in[3];
    const float* bk = (const float*)d_in[4];
    const float* Wv = (const float*)d_in[5];
    const float* bv = (const float*)d_in[6];
    const float* Wg = (const float*)d_in[7];
    const float* bg = (const float*)d_in[8];
    const float* Wo = (const float*)d_in[9];
    const float* bo = (const float*)d_in[10];
    float* out = (float*)d_out;

    float *pQKGV, *pbcat;
    cudaGetSymbolAddress((void**)&pQKGV, g_QKGV);
    cudaGetSymbolAddress((void**)&pbcat, g_bcat);

    __half *hsh, *hsl, *wth, *wtl, *woh, *wol, *obh, *obl;
    cudaGetSymbolAddress((void**)&hsh, g_hs_hi);
    cudaGetSymbolAddress((void**)&hsl, g_hs_lo);
    cudaGetSymbolAddress((void**)&wth, g_Wt_hi);
    cudaGetSymbolAddress((void**)&wtl, g_Wt_lo);
    cudaGetSymbolAddress((void**)&woh, g_Wot_hi);
    cudaGetSymbolAddress((void**)&wol, g_Wot_lo);
    cudaGetSymbolAddress((void**)&obh, g_ob_hi);
    cudaGetSymbolAddress((void**)&obl, g_ob_lo);

    cudaFuncSetAttribute(tgemm_kernel,
                         cudaFuncAttributeMaxDynamicSharedMemorySize, TG_SMEM_BYTES);

    // launch order chosen so launch #6 (ncu -s 5 -c 1) = merged projection GEMM
    transpose_split_kernel<<<dim3(OO / 32, VV / 32), dim3(32, 8)>>>(Wo, woh, wol, VV, OO);   // 1
    biascat_kernel<<<NPROJ / 256, 256>>>(bq, bk, bg, bv);                                    // 2
    {
        int n4 = (TT * HH) / 8;    // half each
        cvt_split_kernel<<<(n4 + 255) / 256, 256>>>(hs, hsh, hsl, n4);                       // 3
        cvt_split_kernel<<<(n4 + 255) / 256, 256>>>(hs + (size_t)TT * HH / 2,
                                                    hsh + (size_t)TT * HH / 2,
                                                    hsl + (size_t)TT * HH / 2, n4);          // 4
    }
    transpose_split4_kernel<<<dim3(KK / 32, HH / 32, 4), dim3(32, 8)>>>(Wq, Wk, Wg, Wv);     // 5

    // merged projections: C = [q|sig(k)|sig(g)|v], N=2048                                    // 6
    tgemm_kernel<<<dim3(NPROJ / 128, TT / 128), 256, TG_SMEM_BYTES>>>(
        hsh, hsl, wth, wtl, pbcat, pQKGV, TT, NPROJ, HH, 2);

    gates_kernel<<<NCH, KK>>>();                                                             // 7
    p_kernel<<<NCH, dim3(32, 32)>>>();                                                       // 8
    uscan_kernel<<<dim3(KK / 32, VV / 32), 128>>>(out + (size_t)TT * OO);                    // 9
    out_kernel<<<dim3(VV / 128, NCH), 256>>>();                                              // 10

    // output GEMM (3-pass, outs hi/lo)                                                      // 11
    tgemm_kernel<<<dim3(OO / 128, TT / 128), 256, TG_SMEM_BYTES>>>(
        obh, obl, woh, wol, bo, out, TT, OO, VV, 0);
}

// round 17
// speedup vs baseline: 1.1722x; 1.0683x over previous
#include <cuda_runtime.h>
#include <cuda_fp16.h>
#include <cuda_bf16.h>
#include <math.h>
#include <stdint.h>

// Problem dims (fixed)
#define TT 8192
#define HH 2048
#define KK 512
#define VV 512
#define OO 2048
#define CSZ 32
#define NCH (TT / CSZ)   // 256 chunks
#define NPROJ 2048       // q|k|g|v concatenated

// ===================== helpers =====================
__device__ __forceinline__ uint32_t smem_u32(const void* p) {
    uint32_t a;
    asm("{ .reg .u64 t; cvta.to.shared.u64 t, %1; cvt.u32.u64 %0, t; }"
        : "=r"(a) : "l"(p));
    return a;
}
__device__ __forceinline__ void ldm_x4(uint32_t* r, uint32_t addr) {
    asm volatile("ldmatrix.sync.aligned.m8n8.x4.shared.b16 {%0,%1,%2,%3}, [%4];"
                 : "=r"(r[0]), "=r"(r[1]), "=r"(r[2]), "=r"(r[3]) : "r"(addr));
}
__device__ __forceinline__ void mma_f16(float* d, const uint32_t* a, const uint32_t* b) {
    asm volatile(
        "mma.sync.aligned.m16n8k16.row.col.f32.f16.f16.f32 "
        "{%0,%1,%2,%3}, {%4,%5,%6,%7}, {%8,%9}, {%0,%1,%2,%3};"
        : "+f"(d[0]), "+f"(d[1]), "+f"(d[2]), "+f"(d[3])
        : "r"(a[0]), "r"(a[1]), "r"(a[2]), "r"(a[3]), "r"(b[0]), "r"(b[1]));
}
__device__ __forceinline__ void cp16(uint32_t s, const void* g) {
    asm volatile("cp.async.cg.shared.global [%0], [%1], 16;" :: "r"(s), "l"(g));
}
#define CP_COMMIT() asm volatile("cp.async.commit_group;" ::: "memory")
#define CP_WAIT0()  asm volatile("cp.async.wait_group 0;" ::: "memory")
#define CP_WAIT1()  asm volatile("cp.async.wait_group 1;" ::: "memory")

// XOR swizzle on packed 64B rows: permute 16B chunks by (row>>1)&3.
// Keeps 16B alignment; makes ldmatrix 8-row reads hit 8 distinct bank groups.
#define SWZ(a) ((a) ^ ((((a) >> 7) & 3u) << 4))

// ===================== scratch (static __device__, no allocs) =====================
static __device__ float g_QKGV[(size_t)TT * NPROJ];   // q|k|g|v concat, row stride 2048
static __device__ float g_qt  [TT * KK];
static __device__ float g_kt  [TT * KK];
static __device__ float g_kh  [TT * KK];
static __device__ float g_Bend[NCH * KK];
static __device__ float g_P   [NCH * CSZ * CSZ];
static __device__ float g_bcat[NPROJ];
static __device__ __nv_bfloat16 g_Sinb[(size_t)NCH * KK * VV];   // state entering chunk (bf16)

// fp16 split operands
static __device__ __half g_hs_hi [(size_t)TT * HH];
static __device__ __half g_hs_lo [(size_t)TT * HH];
static __device__ __half g_Wt_hi [(size_t)4 * KK * HH];   // stacked Wq,Wk,Wg,Wv^T : [2048,2048]
static __device__ __half g_Wt_lo [(size_t)4 * KK * HH];
static __device__ __half g_Wot_hi[(size_t)OO * VV];       // [2048,512]
static __device__ __half g_Wot_lo[(size_t)OO * VV];
static __device__ __half g_ob_hi [(size_t)TT * VV];
static __device__ __half g_ob_lo [(size_t)TT * VV];

// ===================== small prep kernels =====================
__global__ void biascat_kernel(const float* __restrict__ bq, const float* __restrict__ bk,
                               const float* __restrict__ bg, const float* __restrict__ bv)
{
    int i = blockIdx.x * 256 + threadIdx.x;   // 0..2047
    float v;
    int p = i >> 9, c = i & 511;
    if (p == 0) v = bq[c]; else if (p == 1) v = bk[c];
    else if (p == 2) v = bg[c]; else v = bv[c];
    g_bcat[i] = v;
}

__global__ void cvt_split_kernel(const float* __restrict__ x,
                                 __half* __restrict__ hi,
                                 __half* __restrict__ lo, int n4)
{
    int i = blockIdx.x * 256 + threadIdx.x;
    if (i >= n4) return;
    float4 v = *((const float4*)x + i);
    __half h0 = __float2half_rn(v.x), h1 = __float2half_rn(v.y);
    __half h2 = __float2half_rn(v.z), h3 = __float2half_rn(v.w);
    __half l0 = __float2half_rn(v.x - __half2float(h0));
    __half l1 = __float2half_rn(v.y - __half2float(h1));
    __half l2 = __float2half_rn(v.z - __half2float(h2));
    __half l3 = __float2half_rn(v.w - __half2float(h3));
    ushort4 uh, ul;
    uh.x = reinterpret_cast<unsigned short&>(h0); uh.y = reinterpret_cast<unsigned short&>(h1);
    uh.z = reinterpret_cast<unsigned short&>(h2); uh.w = reinterpret_cast<unsigned short&>(h3);
    ul.x = reinterpret_cast<unsigned short&>(l0); ul.y = reinterpret_cast<unsigned short&>(l1);
    ul.z = reinterpret_cast<unsigned short&>(l2); ul.w = reinterpret_cast<unsigned short&>(l3);
    *((ushort4*)hi + i) = uh;
    *((ushort4*)lo + i) = ul;
}

// W [R, C] fp32 row-major -> out [C, R] fp16 hi/lo (single weight)
__global__ void transpose_split_kernel(const float* __restrict__ W,
                                       __half* __restrict__ hi,
                                       __half* __restrict__ lo,
                                       int R, int Ccols)
{
    __shared__ float tile[32][33];
    int c0 = blockIdx.x * 32, r0 = blockIdx.y * 32;
    int tx = threadIdx.x, ty = threadIdx.y;
#pragma unroll
    for (int i = 0; i < 32; i += 8)
        tile[ty + i][tx] = W[(size_t)(r0 + ty + i) * Ccols + c0 + tx];
    __syncthreads();
#pragma unroll
    for (int i = 0; i < 32; i += 8) {
        float v = tile[tx][ty + i];
        __half h = __float2half_rn(v);
        __half l = __float2half_rn(v - __half2float(h));
        size_t o = (size_t)(c0 + ty + i) * R + r0 + tx;
        hi[o] = h; lo[o] = l;
    }
}

// batched: transpose/split Wq,Wk,Wg,Wv [2048,512] -> stacked [4*512, 2048]
__global__ void transpose_split4_kernel(const float* __restrict__ W0, const float* __restrict__ W1,
                                        const float* __restrict__ W2, const float* __restrict__ W3)
{
    __shared__ float tile[32][33];
    const float* W = (blockIdx.z == 0) ? W0 : (blockIdx.z == 1) ? W1
                   : (blockIdx.z == 2) ? W2 : W3;
    __half* hi = g_Wt_hi + (size_t)blockIdx.z * KK * HH;
    __half* lo = g_Wt_lo + (size_t)blockIdx.z * KK * HH;
    int c0 = blockIdx.x * 32, r0 = blockIdx.y * 32;   // c: out-col (K dim), r: H dim
    int tx = threadIdx.x, ty = threadIdx.y;
#pragma unroll
    for (int i = 0; i < 32; i += 8)
        tile[ty + i][tx] = W[(size_t)(r0 + ty + i) * KK + c0 + tx];
    __syncthreads();
#pragma unroll
    for (int i = 0; i < 32; i += 8) {
        float v = tile[tx][ty + i];
        __half h = __float2half_rn(v);
        __half l = __float2half_rn(v - __half2float(h));
        size_t o = (size_t)(c0 + ty + i) * HH + r0 + tx;
        hi[o] = h; lo[o] = l;
    }
}

// ===================== tensor-core GEMM via mma.sync (fp16 hi/lo, 3 passes) ======
// C[M,N] = act(A @ B^T + bias); A: [M,Kd] fp16 hi/lo, B: [N,Kd] fp16 hi/lo
// actmode: 0 none; 1 sigmoid all; 2 sigmoid iff (blockIdx.x>>2) in {1,2} (k,g ranges)
// CTA tile 128x128, BK=32 packed rows (64B) + XOR swizzle, 3-stage cp.async
// pipeline, 2 CTAs/SM.
#define BK   32
#define TILE_B (128 * 64)          // bytes per tile (128 rows x 64B)
#define STAGE_B (4 * TILE_B)       // Ahi,Alo,Bhi,Blo per stage = 32768 B
#define NSTAGE 3
#define TG_SMEM_BYTES (NSTAGE * STAGE_B)   // 98304

__global__ __launch_bounds__(256, 2) void tgemm_kernel(
    const __half* __restrict__ Ahi, const __half* __restrict__ Alo,
    const __half* __restrict__ Bhi, const __half* __restrict__ Blo,
    const float* __restrict__ bias, float* __restrict__ C,
    int M, int N, int Kd, int actmode)
{
    extern __shared__ __half sm[];      // [3 stages][4 tiles][TILE_B bytes]
    const uint32_t s0 = smem_u32(sm);

    int tid = threadIdx.x, lane = tid & 31, wid = tid >> 5;
    int bm = blockIdx.y * 128, bn = blockIdx.x * 128;
    int wm = (wid & 3) * 32, wn = (wid >> 2) * 64;
    int act = (actmode == 1) || (actmode == 2 && ((blockIdx.x >> 2) == 1 || (blockIdx.x >> 2) == 2));

    // ldgsts slots: thread covers rows rr and rr+64, col-chunk qq (16B = 8 fp16)
    int rr = tid >> 2, qq = tid & 3;
    size_t gA  = (size_t)(bm + rr) * Kd + qq * 8;
    size_t gA2 = gA + (size_t)64 * Kd;
    size_t gB  = (size_t)(bn + rr) * Kd + qq * 8;
    size_t gB2 = gB + (size_t)64 * Kd;
    uint32_t so  = SWZ((uint32_t)(rr * 64 + qq * 16));
    uint32_t so2 = SWZ((uint32_t)((rr + 64) * 64 + qq * 16));

    auto issue = [&](int ch) {
        size_t kb = (size_t)ch << 5;
        uint32_t sb = s0 + (uint32_t)(ch % NSTAGE) * STAGE_B;
        cp16(sb + 0 * TILE_B + so,  Ahi + gA  + kb);
        cp16(sb + 0 * TILE_B + so2, Ahi + gA2 + kb);
        cp16(sb + 1 * TILE_B + so,  Alo + gA  + kb);
        cp16(sb + 1 * TILE_B + so2, Alo + gA2 + kb);
        cp16(sb + 2 * TILE_B + so,  Bhi + gB  + kb);
        cp16(sb + 2 * TILE_B + so2, Bhi + gB2 + kb);
        cp16(sb + 3 * TILE_B + so,  Blo + gB  + kb);
        cp16(sb + 3 * TILE_B + so2, Blo + gB2 + kb);
        CP_COMMIT();
    };

    // fragment base offsets (pre-swizzle, bytes, relative to stage base)
    uint32_t a_base = (uint32_t)((wm + (lane & 15)) * 64 + ((lane >> 4) << 4));
    uint32_t b_base = (uint32_t)((wn + ((lane >> 4) << 3) + (lane & 7)) * 64
                                 + (((lane >> 3) & 1) << 4));

    float acc[2][8][4];
#pragma unroll
    for (int i = 0; i < 2; i++)
#pragma unroll
        for (int j = 0; j < 8; j++)
#pragma unroll
            for (int l = 0; l < 4; l++) acc[i][j][l] = 0.f;

    const int NC = Kd >> 5;

    issue(0);
    issue(1);

    for (int ch = 0; ch < NC; ch++) {
        // stage ch ready when at most 1 newer group still pending
        if (ch + 1 < NC) CP_WAIT1(); else CP_WAIT0();
        __syncthreads();                  // all warps done with stage (ch-1)%3 too
        if (ch + 2 < NC) issue(ch + 2);   // deep prefetch, lands ~1 chunk later

        uint32_t base = s0 + (uint32_t)(ch % NSTAGE) * STAGE_B;
#pragma unroll
        for (int ks = 0; ks < 2; ks++) {
            uint32_t ksb = (uint32_t)(ks * 32);
            uint32_t ah[2][4], al[2][4];
#pragma unroll
            for (int mf = 0; mf < 2; mf++) {
                uint32_t ao = SWZ(a_base + (uint32_t)(mf * 16 * 64) + ksb);
                ldm_x4(ah[mf], base + 0 * TILE_B + ao);
                ldm_x4(al[mf], base + 1 * TILE_B + ao);
            }
#pragma unroll
            for (int nfp = 0; nfp < 4; nfp++) {
                uint32_t bo = SWZ(b_base + (uint32_t)(nfp * 16 * 64) + ksb);
                uint32_t bh[4], bl[4];
                ldm_x4(bh, base + 2 * TILE_B + bo);
                ldm_x4(bl, base + 3 * TILE_B + bo);
#pragma unroll
                for (int h = 0; h < 2; h++) {
                    int nf = nfp * 2 + h;
#pragma unroll
                    for (int mf = 0; mf < 2; mf++) {
                        mma_f16(acc[mf][nf], ah[mf], bh + 2 * h);
                        mma_f16(acc[mf][nf], ah[mf], bl + 2 * h);
                        mma_f16(acc[mf][nf], al[mf], bh + 2 * h);
                    }
                }
            }
        }
    }

    // epilogue
    int crow = lane >> 2, ccol = (lane & 3) * 2;
#pragma unroll
    for (int mf = 0; mf < 2; mf++) {
#pragma unroll
        for (int nf = 0; nf < 8; nf++) {
            int row = bm + wm + mf * 16 + crow;
            int col = bn + wn + nf * 8 + ccol;
            float b0 = bias[col], b1 = bias[col + 1];
            float2 o0, o1;
            o0.x = acc[mf][nf][0] + b0;
            o0.y = acc[mf][nf][1] + b1;
            o1.x = acc[mf][nf][2] + b0;
            o1.y = acc[mf][nf][3] + b1;
            if (act) {
                o0.x = 1.f / (1.f + expf(-o0.x));
                o0.y = 1.f / (1.f + expf(-o0.y));
                o1.x = 1.f / (1.f + expf(-o1.x));
                o1.y = 1.f / (1.f + expf(-o1.y));
            }
            *(float2*)(C + (size_t)row * N + col)       = o0;
            *(float2*)(C + (size_t)(row + 8) * N + col) = o1;
        }
    }
}

// ===================== middle kernels =====================
// reads q,k,g from concat buffer (stride NPROJ)
__global__ void gates_kernel()
{
    int c = blockIdx.x;
    int col = threadIdx.x;
    size_t base  = (size_t)c * CSZ * NPROJ + col;   // q plane
    size_t baseo = (size_t)c * CSZ * KK + col;      // outputs
    float gs[CSZ];
    float cum = 1.f;
#pragma unroll
    for (int t = 0; t < CSZ; t++) {
        size_t idx = base + (size_t)t * NPROJ;
        size_t odx = baseo + (size_t)t * KK;
        float g = g_QKGV[idx + 1024];
        float k = g_QKGV[idx + 512];
        gs[t] = g;
        cum *= g;
        g_qt[odx] = g_QKGV[idx] * cum;
        g_kt[odx] = k / cum;
    }
    g_Bend[c * KK + col] = cum;
    float suf = 1.f;
#pragma unroll
    for (int t = CSZ - 1; t >= 0; t--) {
        size_t idx = base + (size_t)t * NPROJ;
        size_t odx = baseo + (size_t)t * KK;
        g_kh[odx] = g_QKGV[idx + 512] * suf;
        suf *= gs[t];
    }
}

__global__ void p_kernel()
{
    int c = blockIdx.x;
    int s = threadIdx.x, t = threadIdx.y;
    int lid = t * 32 + s;
    __shared__ float Qs[CSZ][65];
    __shared__ float Ks[CSZ][65];
    float acc = 0.f;
    for (int kb = 0; kb < KK; kb += 64) {
#pragma unroll
        for (int i = 0; i < 2; i++) {
            int e = lid + i * 1024;
            int r = e >> 6, cc = e & 63;
            Qs[r][cc] = g_qt[(size_t)(c * CSZ + r) * KK + kb + cc];
            Ks[r][cc] = g_kt[(size_t)(c * CSZ + r) * KK + kb + cc];
        }
        __syncthreads();
        if (t >= s) {
#pragma unroll
            for (int kk = 0; kk < 64; kk++) acc += Qs[t][kk] * Ks[s][kk];
        }
        __syncthreads();
    }
    g_P[(c * CSZ + t) * CSZ + s] = (t >= s) ? acc : 0.f;
}

// ===================== fused U + inter-chunk scan =====================
__global__ __launch_bounds__(128) void uscan_kernel(float* __restrict__ final_state)
{
    __shared__ __align__(16) float sKh[2][CSZ][32];   // [buf][t][k]
    __shared__ __align__(16) float sV [2][CSZ][32];   // [buf][t][v]

    const int kt = blockIdx.x * 32;
    const int vt = blockIdx.y * 32;
    const int tid = threadIdx.x;
    const int k0 = (tid >> 3) * 2;   // 2 k-rows per thread
    const int v0 = (tid & 7) * 4;    // 4 v-cols per thread

    const uint32_t sKhB = smem_u32(&sKh[0][0][0]);
    const uint32_t sVB  = smem_u32(&sV[0][0][0]);
    const uint32_t BUFB = CSZ * 32 * 4;   // 4096 bytes per buffer

    float S0[4] = {0.f, 0.f, 0.f, 0.f};
    float S1[4] = {0.f, 0.f, 0.f, 0.f};

    auto issue = [&](int c, int buf) {
#pragma unroll
        for (int i = 0; i < 2; i++) {
            int e = tid + i * 128;
            int r = e >> 3, q = (e & 7) * 4;
            uint32_t off = (uint32_t)(buf) * BUFB + (uint32_t)(r * 32 + q) * 4;
            cp16(sKhB + off, g_kh + (size_t)(c * CSZ + r) * KK + kt + q);
            cp16(sVB  + off, g_QKGV + (size_t)(c * CSZ + r) * NPROJ + 1536 + vt + q);
        }
        CP_COMMIT();
    };

    issue(0, 0);
    for (int c = 0; c < NCH; c++) {
        int buf = c & 1;
        if (c + 1 < NCH) { issue(c + 1, buf ^ 1); CP_WAIT1(); }
        else             { CP_WAIT0(); }
        __syncthreads();

        float b0 = g_Bend[c * KK + kt + k0];
        float b1 = g_Bend[c * KK + kt + k0 + 1];

        float U0[4] = {0.f, 0.f, 0.f, 0.f};
        float U1[4] = {0.f, 0.f, 0.f, 0.f};
#pragma unroll 8
        for (int t = 0; t < CSZ; t++) {
            float a0 = sKh[buf][t][k0];
            float a1 = sKh[buf][t][k0 + 1];
            float4 vv = *(const float4*)&sV[buf][t][v0];
            U0[0] += a0 * vv.x; U0[1] += a0 * vv.y;
            U0[2] += a0 * vv.z; U0[3] += a0 * vv.w;
            U1[0] += a1 * vv.x; U1[1] += a1 * vv.y;
            U1[2] += a1 * vv.z; U1[3] += a1 * vv.w;
        }

        // store Sin (state BEFORE this chunk) as bf16
        {
            ushort4 p0, p1;
            __nv_bfloat16 h;
            h = __float2bfloat16(S0[0]); p0.x = reinterpret_cast<unsigned short&>(h);
            h = __float2bfloat16(S0[1]); p0.y = reinterpret_cast<unsigned short&>(h);
            h = __float2bfloat16(S0[2]); p0.z = reinterpret_cast<unsigned short&>(h);
            h = __float2bfloat16(S0[3]); p0.w = reinterpret_cast<unsigned short&>(h);
            h = __float2bfloat16(S1[0]); p1.x = reinterpret_cast<unsigned short&>(h);
            h = __float2bfloat16(S1[1]); p1.y = reinterpret_cast<unsigned short&>(h);
            h = __float2bfloat16(S1[2]); p1.z = reinterpret_cast<unsigned short&>(h);
            h = __float2bfloat16(S1[3]); p1.w = reinterpret_cast<unsigned short&>(h);
            *(ushort4*)(g_Sinb + ((size_t)c * KK + kt + k0)     * VV + vt + v0) = p0;
            *(ushort4*)(g_Sinb + ((size_t)c * KK + kt + k0 + 1) * VV + vt + v0) = p1;
        }

#pragma unroll
        for (int j = 0; j < 4; j++) {
            S0[j] = b0 * S0[j] + U0[j];
            S1[j] = b1 * S1[j] + U1[j];
        }
        __syncthreads();   // compute done before next issue overwrites buf
    }

    *(float4*)(final_state + (size_t)(kt + k0)     * VV + vt + v0) = *(float4*)S0;
    *(float4*)(final_state + (size_t)(kt + k0 + 1) * VV + vt + v0) = *(float4*)S1;
}

// Out_c = Q~_c @ S_in[c] + P_c @ V_c ; emits fp16 hi/lo for final GEMM (3-pass)
__global__ __launch_bounds__(256) void out_kernel()
{
    int c = blockIdx.y;
    int vb = blockIdx.x * 128;
    int lid = threadIdx.x;
    int tr = lid >> 4, tc = lid & 15;
    __shared__ __align__(16) float Qs[CSZ][36];
    __shared__ __align__(16) float Ss[CSZ][132];
    __shared__ __align__(16) float Ps[CSZ][36];
    __shared__ __align__(16) float Vs[CSZ][132];
    float acc[2][8] = {};
    for (int kb = 0; kb < KK; kb += 32) {
#pragma unroll
        for (int i = 0; i < 4; i++) {
            int e = lid + i * 256;
            int r = e >> 5, cc = e & 31;
            Qs[r][cc] = g_qt[(size_t)(c * CSZ + r) * KK + kb + cc];
        }
#pragma unroll
        for (int i = 0; i < 2; i++) {
            int e = lid + i * 256;
            int r = e >> 4, c8 = e & 15;
            const __nv_bfloat162* p = (const __nv_bfloat162*)
                (g_Sinb + ((size_t)c * KK + kb + r) * VV + vb + c8 * 8);
            uint2 raw0 = *(const uint2*)p;
            uint2 raw1 = *((const uint2*)p + 1);
            __nv_bfloat162 b0 = *(__nv_bfloat162*)&raw0.x;
            __nv_bfloat162 b1 = *(__nv_bfloat162*)&raw0.y;
            __nv_bfloat162 b2 = *(__nv_bfloat162*)&raw1.x;
            __nv_bfloat162 b3 = *(__nv_bfloat162*)&raw1.y;
            float2 f0 = __bfloat1622float2(b0);
            float2 f1 = __bfloat1622float2(b1);
            float2 f2 = __bfloat1622float2(b2);
            float2 f3 = __bfloat1622float2(b3);
            float* d = &Ss[r][c8 * 8];
            d[0] = f0.x; d[1] = f0.y; d[2] = f1.x; d[3] = f1.y;
            d[4] = f2.x; d[5] = f2.y; d[6] = f3.x; d[7] = f3.y;
        }
        __syncthreads();
#pragma unroll
        for (int kk = 0; kk < 32; kk++) {
            float a0 = Qs[tr * 2 + 0][kk];
            float a1 = Qs[tr * 2 + 1][kk];
            float4 w0 = *(const float4*)&Ss[kk][tc * 8];
            float4 w1 = *(const float4*)&Ss[kk][tc * 8 + 4];
            acc[0][0] += a0 * w0.x; acc[0][1] += a0 * w0.y;
            acc[0][2] += a0 * w0.z; acc[0][3] += a0 * w0.w;
            acc[0][4] += a0 * w1.x; acc[0][5] += a0 * w1.y;
            acc[0][6] += a0 * w1.z; acc[0][7] += a0 * w1.w;
            acc[1][0] += a1 * w0.x; acc[1][1] += a1 * w0.y;
            acc[1][2] += a1 * w0.z; acc[1][3] += a1 * w0.w;
            acc[1][4] += a1 * w1.x; acc[1][5] += a1 * w1.y;
            acc[1][6] += a1 * w1.z; acc[1][7] += a1 * w1.w;
        }
        __syncthreads();
    }
#pragma unroll
    for (int i = 0; i < 4; i++) {
        int e = lid + i * 256;
        int r = e >> 5, cc = e & 31;
        Ps[r][cc] = g_P[(c * CSZ + r) * CSZ + cc];
    }
#pragma unroll
    for (int i = 0; i < 4; i++) {
        int e = lid + i * 256;
        int r = e >> 5, c4 = e & 31;
        float4 v = *(const float4*)(g_QKGV + (size_t)(c * CSZ + r) * NPROJ + 1536 + vb + c4 * 4);
        *(float4*)(&Vs[r][c4 * 4]) = v;
    }
    __syncthreads();
#pragma unroll
    for (int ss = 0; ss < CSZ; ss++) {
        float a0 = Ps[tr * 2 + 0][ss];
        float a1 = Ps[tr * 2 + 1][ss];
        float4 w0 = *(const float4*)&Vs[ss][tc * 8];
        float4 w1 = *(const float4*)&Vs[ss][tc * 8 + 4];
        acc[0][0] += a0 * w0.x; acc[0][1] += a0 * w0.y;
        acc[0][2] += a0 * w0.z; acc[0][3] += a0 * w0.w;
        acc[0][4] += a0 * w1.x; acc[0][5] += a0 * w1.y;
        acc[0][6] += a0 * w1.z; acc[0][7] += a0 * w1.w;
        acc[1][0] += a1 * w0.x; acc[1][1] += a1 * w0.y;
        acc[1][2] += a1 * w0.z; acc[1][3] += a1 * w0.w;
        acc[1][4] += a1 * w1.x; acc[1][5] += a1 * w1.y;
        acc[1][6] += a1 * w1.z; acc[1][7] += a1 * w1.w;
    }
    // write fp16 hi/lo (final GEMM runs 3-pass)
#pragma unroll
    for (int i = 0; i < 2; i++) {
        int t = tr * 2 + i;
        size_t o = (size_t)(c * CSZ + t) * VV + vb + tc * 8;
        unsigned short ph[8], pl[8];
#pragma unroll
        for (int j = 0; j < 8; j++) {
            float v = acc[i][j];
            __half h = __float2half_rn(v);
            __half l = __float2half_rn(v - __half2float(h));
            ph[j] = reinterpret_cast<unsigned short&>(h);
            pl[j] = reinterpret_cast<unsigned short&>(l);
        }
        *(uint4*)(g_ob_hi + o) = *(uint4*)ph;
        *(uint4*)(g_ob_lo + o) = *(uint4*)pl;
    }
}

// ===================== launch =====================
extern "C" void kernel_launch(void* const* d_in, const int* in_sizes, int n_in,
                              void* d_out, int out_size)
{
    const float* hs = (const float*)d_in[0];
    const float* Wq = (const float*)d_in[1];
    const float* bq = (const float*)d_in[2];
    const float* Wk = (const float*)d_in[3];
    const float* bk = (const float*)d_in[4];
    const float* Wv = (const float*)d_in[5];
    const float* bv = (const float*)d_in[6];
    const float* Wg = (const float*)d_in[7];
    const float* bg = (const float*)d_in[8];
    const float* Wo = (const float*)d_in[9];
    const float* bo = (const float*)d_in[10];
    float* out = (float*)d_out;

    float *pQKGV, *pbcat;
    cudaGetSymbolAddress((void**)&pQKGV, g_QKGV);
    cudaGetSymbolAddress((void**)&pbcat, g_bcat);

    __half *hsh, *hsl, *wth, *wtl, *woh, *wol, *obh, *obl;
    cudaGetSymbolAddress((void**)&hsh, g_hs_hi);
    cudaGetSymbolAddress((void**)&hsl, g_hs_lo);
    cudaGetSymbolAddress((void**)&wth, g_Wt_hi);
    cudaGetSymbolAddress((void**)&wtl, g_Wt_lo);
    cudaGetSymbolAddress((void**)&woh, g_Wot_hi);
    cudaGetSymbolAddress((void**)&wol, g_Wot_lo);
    cudaGetSymbolAddress((void**)&obh, g_ob_hi);
    cudaGetSymbolAddress((void**)&obl, g_ob_lo);

    cudaFuncSetAttribute(tgemm_kernel,
                         cudaFuncAttributeMaxDynamicSharedMemorySize, TG_SMEM_BYTES);

    transpose_split_kernel<<<dim3(OO / 32, VV / 32), dim3(32, 8)>>>(Wo, woh, wol, VV, OO);
    biascat_kernel<<<NPROJ / 256, 256>>>(bq, bk, bg, bv);
    {
        int n4 = (TT * HH) / 8;    // half each
        cvt_split_kernel<<<(n4 + 255) / 256, 256>>>(hs, hsh, hsl, n4);
        cvt_split_kernel<<<(n4 + 255) / 256, 256>>>(hs + (size_t)TT * HH / 2,
                                                    hsh + (size_t)TT * HH / 2,
                                                    hsl + (size_t)TT * HH / 2, n4);
    }
    transpose_split4_kernel<<<dim3(KK / 32, HH / 32, 4), dim3(32, 8)>>>(Wq, Wk, Wg, Wv);

    // merged projections: C = [q|sig(k)|sig(g)|v], N=2048
    tgemm_kernel<<<dim3(NPROJ / 128, TT / 128), 256, TG_SMEM_BYTES>>>(
        hsh, hsl, wth, wtl, pbcat, pQKGV, TT, NPROJ, HH, 2);

    gates_kernel<<<NCH, KK>>>();
    p_kernel<<<NCH, dim3(32, 32)>>>();
    uscan_kernel<<<dim3(KK / 32, VV / 32), 128>>>(out + (size_t)TT * OO);
    out_kernel<<<dim3(VV / 128, NCH), 256>>>();

    // output GEMM (3-pass, outs hi/lo)
    tgemm_kernel<<<dim3(OO / 128, TT / 128), 256, TG_SMEM_BYTES>>>(
        obh, obl, woh, wol, bo, out, TT, OO, VV, 0);
}